// round 2
// baseline (speedup 1.0000x reference)
#include <cuda_runtime.h>
#include <cstdint>

#define N_NODES 50000
#define D 128
#define E_EDGES 800000

// Scratch (device globals: allocation is forbidden). 16B-aligned for float4/red.v4.
__device__ __align__(16) float g_node[N_NODES * D];   // x @ Wn^T + bn
__device__ __align__(16) float g_nbr [N_NODES * D];   // segment_sum(node[dst], src)
__device__ __align__(16) float g_es  [N_NODES * D];   // edge_sum (pre-gelu)
__device__ __align__(16) float g_deg [N_NODES];       // out-degree (float)
__device__ __align__(16) float g_WnT [D * D];         // Wn^T      [K=128][N=128]
__device__ __align__(16) float g_WeT [2 * D * D];     // We^T      [K=256][N=128]
__device__ __align__(16) float g_WuT [3 * D * D];     // Wu^T      [K=384][N=128]

// ---------------------------------------------------------------------------
__global__ void zero_kernel() {
    int i = blockIdx.x * blockDim.x + threadIdx.x;
    float4 z = make_float4(0.f, 0.f, 0.f, 0.f);
    if (i < N_NODES * D / 4) ((float4*)g_nbr)[i] = z;
    if (i < N_NODES) g_deg[i] = 0.f;
}

// Transpose the three weight matrices so GEMM B-loads are coalesced.
__global__ void prep_weights(const float* __restrict__ Wn,
                             const float* __restrict__ We,
                             const float* __restrict__ Wu) {
    int i = blockIdx.x * blockDim.x + threadIdx.x;
    int k = i / D, n = i % D;
    if (i < D * D)     g_WnT[i] = Wn[n * D + k];          // Wn [D][D]
    if (i < 2 * D * D) g_WeT[i] = We[n * 2 * D + k];      // We [D][2D]
    if (i < 3 * D * D) g_WuT[i] = Wu[n * 3 * D + k];      // Wu [D][3D]
}

// ---------------------------------------------------------------------------
// Edge scatter: one warp per edge.
//   nbr_sum[src] += node[dst]   (red.global.add.v4.f32, 1 per lane)
//   deg[src]     += 1           (lane 0)
__global__ void __launch_bounds__(256) scatter_kernel(const int* __restrict__ ei) {
    int w = (blockIdx.x * blockDim.x + threadIdx.x) >> 5;
    if (w >= E_EDGES) return;
    int lane = threadIdx.x & 31;
    int src = ei[w];
    int dst = ei[E_EDGES + w];
    float4 v = ((const float4*)(g_node + (size_t)dst * D))[lane];
    float* p = g_nbr + (size_t)src * D + lane * 4;
    asm volatile("red.global.add.v4.f32 [%0], {%1, %2, %3, %4};"
                 :: "l"(p), "f"(v.x), "f"(v.y), "f"(v.z), "f"(v.w) : "memory");
    if (lane == 0) atomicAdd(&g_deg[src], 1.0f);
}

// ---------------------------------------------------------------------------
__device__ __forceinline__ float gelu_exact(float u) {
    return 0.5f * u * (1.0f + erff(u * 0.70710678118654752f));
}

// Register-tiled fp32 GEMM: C[M x 128] = A[M x K] @ BT[K x 128] + bias
// MODE 0: A = x,                        BT = Wn^T, C = g_node, bias = bn
// MODE 1: A = [deg*node | nbr],         BT = We^T, C = g_es,   bias = deg*be
// MODE 2: A = gelu([node | nbr | es]),  BT = Wu^T, C = d_out,  bias = bu
// Tile: BM=64, BN=128, BK=16; 256 threads; each thread: 4 rows x 8 cols.
template <int MODE, int K>
__global__ void __launch_bounds__(256) gemm_kernel(const float* __restrict__ A0,
                                                   const float* __restrict__ bias,
                                                   float* __restrict__ Cout) {
    constexpr int BM = 64, BK = 16;
    __shared__ float As[BM][BK + 1];
    __shared__ float Bs[BK][D];

    const float* BT = (MODE == 0) ? g_WnT : (MODE == 1) ? g_WeT : g_WuT;
    int tid = threadIdx.x;
    int ty = tid >> 4, tx = tid & 15;
    int rowBase = blockIdx.x * BM;

    float acc[4][8];
#pragma unroll
    for (int i = 0; i < 4; i++)
#pragma unroll
        for (int j = 0; j < 8; j++) acc[i][j] = 0.f;

    int loadRow = tid >> 2;        // 0..63
    int loadKs  = (tid & 3) * 4;   // 0,4,8,12

    for (int k0 = 0; k0 < K; k0 += BK) {
        // ---- load A tile ----
        int m = rowBase + loadRow;
#pragma unroll
        for (int j = 0; j < 4; j++) {
            int k = k0 + loadKs + j;
            float v = 0.f;
            if (m < N_NODES) {
                if (MODE == 0) {
                    v = A0[(size_t)m * D + k];
                } else if (MODE == 1) {
                    v = (k < D) ? g_deg[m] * g_node[(size_t)m * D + k]
                                : g_nbr[(size_t)m * D + (k - D)];
                } else {
                    int seg = k >> 7, kk = k & 127;
                    float u = (seg == 0) ? g_node[(size_t)m * D + kk]
                            : (seg == 1) ? g_nbr[(size_t)m * D + kk]
                                         : g_es[(size_t)m * D + kk];
                    v = gelu_exact(u);
                }
            }
            As[loadRow][loadKs + j] = v;
        }
        // ---- load B tile (coalesced float4) ----
        {
            const float4* bsrc = (const float4*)(BT + (size_t)k0 * D);
            float4* bdst = (float4*)(&Bs[0][0]);
            bdst[tid]       = bsrc[tid];
            bdst[tid + 256] = bsrc[tid + 256];
        }
        __syncthreads();
        // ---- compute ----
#pragma unroll
        for (int kk = 0; kk < BK; kk++) {
            float a[4], b[8];
#pragma unroll
            for (int i = 0; i < 4; i++) a[i] = As[ty * 4 + i][kk];
#pragma unroll
            for (int j = 0; j < 8; j++) b[j] = Bs[kk][tx * 8 + j];
#pragma unroll
            for (int i = 0; i < 4; i++)
#pragma unroll
                for (int j = 0; j < 8; j++) acc[i][j] += a[i] * b[j];
        }
        __syncthreads();
    }

    // ---- epilogue ----
#pragma unroll
    for (int i = 0; i < 4; i++) {
        int m = rowBase + ty * 4 + i;
        if (m >= N_NODES) continue;
        float bscale = (MODE == 1) ? g_deg[m] : 1.f;
        float* crow = ((MODE == 0) ? g_node : (MODE == 1) ? g_es : Cout) + (size_t)m * D;
#pragma unroll
        for (int j = 0; j < 8; j++) {
            int n = tx * 8 + j;
            crow[n] = acc[i][j] + bscale * bias[n];
        }
    }
}

// ---------------------------------------------------------------------------
extern "C" void kernel_launch(void* const* d_in, const int* in_sizes, int n_in,
                              void* d_out, int out_size) {
    const float* x  = (const float*)d_in[0];
    const int*   ei = (const int*)d_in[1];
    const float* Wn = (const float*)d_in[2];
    const float* bn = (const float*)d_in[3];
    const float* We = (const float*)d_in[4];
    const float* be = (const float*)d_in[5];
    const float* Wu = (const float*)d_in[6];
    const float* bu = (const float*)d_in[7];
    float* out = (float*)d_out;

    (void)in_sizes; (void)n_in; (void)out_size;

    const int gemm_blocks = (N_NODES + 63) / 64;   // 782

    zero_kernel<<<(N_NODES * D / 4 + 255) / 256, 256>>>();
    prep_weights<<<(3 * D * D + 255) / 256, 256>>>(Wn, We, Wu);

    // 1. node = x @ Wn^T + bn
    gemm_kernel<0, 128><<<gemm_blocks, 256>>>(x, bn, nullptr);

    // 2. nbr_sum / deg scatter (one warp per edge)
    scatter_kernel<<<(E_EDGES * 32 + 255) / 256, 256>>>(ei);

    // 3. edge_sum = [deg*node | nbr] @ We^T + deg*be
    gemm_kernel<1, 256><<<gemm_blocks, 256>>>(nullptr, be, nullptr);

    // 4. out = gelu([node | nbr | edge_sum]) @ Wu^T + bu
    gemm_kernel<2, 384><<<gemm_blocks, 256>>>(nullptr, bu, out);
}

// round 7
// speedup vs baseline: 2.2764x; 2.2764x over previous
#include <cuda_runtime.h>
#include <cuda_bf16.h>
#include <cstdint>

#define N_NODES 50000
#define D 128
#define E_EDGES 800000
#define M_TILE 128
#define N_TILES ((N_NODES + M_TILE - 1) / M_TILE)   // 391
#define PADK 40                                      // padded row: 40 bf16 = 80B (16B-aligned, conflict-free ldmatrix)

// ---------------- scratch globals (allocation forbidden) -------------------
__device__ __align__(16) float g_node[N_NODES * D];
__device__ __align__(16) float g_nbr [N_NODES * D];
__device__ __align__(16) float g_es  [N_NODES * D];
__device__ __align__(16) float g_deg [N_NODES];
__device__ __align__(16) __nv_bfloat16 g_Wn_h[D *     D];
__device__ __align__(16) __nv_bfloat16 g_Wn_l[D *     D];
__device__ __align__(16) __nv_bfloat16 g_We_h[D * 2 * D];
__device__ __align__(16) __nv_bfloat16 g_We_l[D * 2 * D];
__device__ __align__(16) __nv_bfloat16 g_Wu_h[D * 3 * D];
__device__ __align__(16) __nv_bfloat16 g_Wu_l[D * 3 * D];

// ---------------- helpers ---------------------------------------------------
__device__ __forceinline__ uint32_t smem_u32(const void* p) {
    uint32_t a;
    asm("{ .reg .u64 t; cvta.to.shared.u64 t, %1; cvt.u32.u64 %0, t; }"
        : "=r"(a) : "l"(p));
    return a;
}
__device__ __forceinline__ void sts128(uint32_t addr, uint4 v) {
    asm volatile("st.shared.v4.b32 [%0], {%1, %2, %3, %4};"
                 :: "r"(addr), "r"(v.x), "r"(v.y), "r"(v.z), "r"(v.w) : "memory");
}
__device__ __forceinline__ void ldsm_x4(uint32_t* r, uint32_t addr) {
    asm volatile("ldmatrix.sync.aligned.m8n8.x4.shared.b16 {%0, %1, %2, %3}, [%4];"
                 : "=r"(r[0]), "=r"(r[1]), "=r"(r[2]), "=r"(r[3]) : "r"(addr));
}
__device__ __forceinline__ void mma16816(float* d, const uint32_t* a, const uint32_t* b) {
    asm volatile(
        "mma.sync.aligned.m16n8k16.row.col.f32.bf16.bf16.f32 "
        "{%0, %1, %2, %3}, {%4, %5, %6, %7}, {%8, %9}, {%0, %1, %2, %3};"
        : "+f"(d[0]), "+f"(d[1]), "+f"(d[2]), "+f"(d[3])
        : "r"(a[0]), "r"(a[1]), "r"(a[2]), "r"(a[3]), "r"(b[0]), "r"(b[1]));
}
__device__ __forceinline__ void split2(float a, float b, uint32_t& hi, uint32_t& lo) {
    __nv_bfloat16 ah = __float2bfloat16(a), bh = __float2bfloat16(b);
    float ar = a - __bfloat162float(ah);
    float br = b - __bfloat162float(bh);
    __nv_bfloat162 h, l;
    h.x = ah; h.y = bh;
    l.x = __float2bfloat16(ar); l.y = __float2bfloat16(br);
    hi = *reinterpret_cast<uint32_t*>(&h);
    lo = *reinterpret_cast<uint32_t*>(&l);
}
__device__ __forceinline__ float gelu_exact(float u) {
    return 0.5f * u * (1.0f + erff(u * 0.70710678118654752f));
}

// ---------------------------------------------------------------------------
__global__ void zero_kernel() {
    int i = blockIdx.x * blockDim.x + threadIdx.x;
    float4 z = make_float4(0.f, 0.f, 0.f, 0.f);
    if (i < N_NODES * D / 4) ((float4*)g_nbr)[i] = z;
    if (i < N_NODES) g_deg[i] = 0.f;
}

// Split weights to bf16 hi/lo; layout stays [n][K] (K-major = mma ".col" B).
__global__ void prep_weights(const float* __restrict__ Wn,
                             const float* __restrict__ We,
                             const float* __restrict__ Wu) {
    int i = blockIdx.x * blockDim.x + threadIdx.x;
    if (i < D * D) {
        float w = Wn[i];
        __nv_bfloat16 h = __float2bfloat16(w);
        g_Wn_h[i] = h; g_Wn_l[i] = __float2bfloat16(w - __bfloat162float(h));
    }
    if (i < 2 * D * D) {
        float w = We[i];
        __nv_bfloat16 h = __float2bfloat16(w);
        g_We_h[i] = h; g_We_l[i] = __float2bfloat16(w - __bfloat162float(h));
    }
    if (i < 3 * D * D) {
        float w = Wu[i];
        __nv_bfloat16 h = __float2bfloat16(w);
        g_Wu_h[i] = h; g_Wu_l[i] = __float2bfloat16(w - __bfloat162float(h));
    }
}

// ---------------------------------------------------------------------------
// Edge scatter: 4 edges per warp (MLP=4 on the row gathers).
__global__ void __launch_bounds__(256) scatter_kernel(const int* __restrict__ ei) {
    int w = (blockIdx.x * blockDim.x + threadIdx.x) >> 5;
    int lane = threadIdx.x & 31;
    int e0 = w * 4;
    if (e0 >= E_EDGES) return;
    int4 s4 = *(const int4*)(ei + e0);
    int4 d4 = *(const int4*)(ei + E_EDGES + e0);
    int src[4] = {s4.x, s4.y, s4.z, s4.w};
    int dst[4] = {d4.x, d4.y, d4.z, d4.w};
    float4 v[4];
#pragma unroll
    for (int i = 0; i < 4; i++)
        v[i] = ((const float4*)(g_node + (size_t)dst[i] * D))[lane];
#pragma unroll
    for (int i = 0; i < 4; i++) {
        float* p = g_nbr + (size_t)src[i] * D + lane * 4;
        asm volatile("red.global.add.v4.f32 [%0], {%1, %2, %3, %4};"
                     :: "l"(p), "f"(v[i].x), "f"(v[i].y), "f"(v[i].z), "f"(v[i].w)
                     : "memory");
    }
    if (lane == 0) {
#pragma unroll
        for (int i = 0; i < 4; i++) atomicAdd(&g_deg[src[i]], 1.0f);
    }
}

// ---------------------------------------------------------------------------
// Split-bf16 HMMA GEMM: C[M x 128] = A[M x K] @ W[128][K]^T + bias
// MODE 0: A = x,                        W = Wn, C = g_node, bias = bn
// MODE 1: A = [deg*node | nbr],         W = We, C = g_es,   bias = deg*be
// MODE 2: A = gelu([node | nbr | es]),  W = Wu, C = d_out,  bias = bu
// CTA: 128x128 tile, 256 threads, 8 warps (4x2), warp tile 32x64, BK=32.
template <int MODE, int K>
__global__ void __launch_bounds__(256) mma_gemm(const float* __restrict__ A0,
                                                const float* __restrict__ bias,
                                                float* __restrict__ Cout) {
    __shared__ __align__(16) __nv_bfloat16 sAh[M_TILE * PADK];
    __shared__ __align__(16) __nv_bfloat16 sAl[M_TILE * PADK];
    __shared__ __align__(16) __nv_bfloat16 sBh[D * PADK];
    __shared__ __align__(16) __nv_bfloat16 sBl[D * PADK];

    const int tid  = threadIdx.x;
    const int lane = tid & 31;
    const int wid  = tid >> 5;
    const int wm   = wid >> 1;          // 0..3  (M)
    const int wn   = wid & 1;           // 0..1  (N)
    const int blockRow = blockIdx.x * M_TILE;

    const uint32_t aAh = smem_u32(sAh), aAl = smem_u32(sAl);
    const uint32_t aBh = smem_u32(sBh), aBl = smem_u32(sBl);

    const __nv_bfloat16* WH = (MODE == 0) ? g_Wn_h : (MODE == 1) ? g_We_h : g_Wu_h;
    const __nv_bfloat16* WL = (MODE == 0) ? g_Wn_l : (MODE == 1) ? g_We_l : g_Wu_l;

    // ---- per-thread load duty: A row = tid/2, B row n = tid/2, half = tid&1
    const int ldRow = tid >> 1;
    const int half  = tid & 1;
    const int mA    = blockRow + ldRow;
    const bool mvA  = (mA < N_NODES);
    const float degA = (MODE == 1) ? (mvA ? g_deg[mA] : 0.f) : 1.f;

    constexpr int NC = K / 32;

    float d[2][8][4];
#pragma unroll
    for (int i = 0; i < 2; i++)
#pragma unroll
        for (int j = 0; j < 8; j++)
#pragma unroll
            for (int q = 0; q < 4; q++) d[i][j][q] = 0.f;

    float4 aReg[4];
    uint4  bRegH[2], bRegL[2];

    auto loadChunk = [&](int c) {
        // A: 16 fp32 of row mA
        const float* srcp;
        if (MODE == 0) {
            srcp = A0 + (size_t)mA * D + c * 32;
        } else if (MODE == 1) {
            srcp = (c < 4) ? g_node + (size_t)mA * D + c * 32
                           : g_nbr  + (size_t)mA * D + (c - 4) * 32;
        } else {
            int seg = c >> 2;
            const float* b = (seg == 0) ? g_node : (seg == 1) ? g_nbr : g_es;
            srcp = b + (size_t)mA * D + (c & 3) * 32;
        }
        const float4* p4 = (const float4*)(srcp + half * 16);
        if (mvA) {
#pragma unroll
            for (int q = 0; q < 4; q++) aReg[q] = p4[q];
        } else {
            float4 z = make_float4(0.f, 0.f, 0.f, 0.f);
#pragma unroll
            for (int q = 0; q < 4; q++) aReg[q] = z;
        }
        // B: 16 bf16 hi + 16 lo of weight row n = ldRow
        const uint4* ph = (const uint4*)(WH + (size_t)ldRow * K + c * 32 + half * 16);
        const uint4* pl = (const uint4*)(WL + (size_t)ldRow * K + c * 32 + half * 16);
        bRegH[0] = ph[0]; bRegH[1] = ph[1];
        bRegL[0] = pl[0]; bRegL[1] = pl[1];
    };

    auto storeChunk = [&](int c) {
        float scale = 1.f;
        if (MODE == 1) scale = (c < 4) ? degA : 1.f;
#pragma unroll
        for (int q = 0; q < 2; q++) {
            float4 fa = aReg[2 * q], fb = aReg[2 * q + 1];
            if (MODE == 1) {
                fa.x *= scale; fa.y *= scale; fa.z *= scale; fa.w *= scale;
                fb.x *= scale; fb.y *= scale; fb.z *= scale; fb.w *= scale;
            }
            if (MODE == 2) {
                fa.x = gelu_exact(fa.x); fa.y = gelu_exact(fa.y);
                fa.z = gelu_exact(fa.z); fa.w = gelu_exact(fa.w);
                fb.x = gelu_exact(fb.x); fb.y = gelu_exact(fb.y);
                fb.z = gelu_exact(fb.z); fb.w = gelu_exact(fb.w);
            }
            uint4 H, L;
            split2(fa.x, fa.y, H.x, L.x);
            split2(fa.z, fa.w, H.y, L.y);
            split2(fb.x, fb.y, H.z, L.z);
            split2(fb.z, fb.w, H.w, L.w);
            uint32_t off = (uint32_t)ldRow * 80u + half * 32u + q * 16u;
            sts128(aAh + off, H);
            sts128(aAl + off, L);
        }
        uint32_t offB = (uint32_t)ldRow * 80u + half * 32u;
        sts128(aBh + offB,      bRegH[0]);
        sts128(aBh + offB + 16, bRegH[1]);
        sts128(aBl + offB,      bRegL[0]);
        sts128(aBl + offB + 16, bRegL[1]);
    };

    loadChunk(0);

    for (int c = 0; c < NC; c++) {
        storeChunk(c);
        __syncthreads();
        if (c + 1 < NC) loadChunk(c + 1);   // overlap LDG with MMAs below

#pragma unroll
        for (int ks = 0; ks < 2; ks++) {
            // ---- A fragments (hi & lo), 2 m-tiles ----
            uint32_t ah[2][4], al[2][4];
            {
                uint32_t kb = (uint32_t)(ks * 16 + ((lane >> 4) << 3)) * 2u;
#pragma unroll
                for (int i = 0; i < 2; i++) {
                    uint32_t r = (uint32_t)(wm * 32 + i * 16 + (lane & 15));
                    uint32_t off = r * 80u + kb;
                    ldsm_x4(ah[i], aAh + off);
                    ldsm_x4(al[i], aAl + off);
                }
            }
            // ---- B fragments (hi & lo), 8 n-tiles via 4 NON-TRANS x4 loads.
            // Storage is [n][K] (K-contiguous) == mma ".col" layout, so the
            // non-trans 8x8 fragment (fixed n, two consecutive k per thread)
            // is exactly the b0/b1 register pattern. Each x4 covers two
            // adjacent 8-wide n-tiles over k0-15:
            //   lanes 0-7:  n rows j*16+0..7,  k+0   -> r0 = b0 (ntile 2j)
            //   lanes 8-15: n rows j*16+0..7,  k+8   -> r1 = b1 (ntile 2j)
            //   lanes 16-23:n rows j*16+8..15, k+0   -> r2 = b0 (ntile 2j+1)
            //   lanes 24-31:n rows j*16+8..15, k+8   -> r3 = b1 (ntile 2j+1)
            uint32_t bh[16], bl[16];
            {
                uint32_t kb = (uint32_t)(ks * 16 + (lane & 8)) * 2u;
#pragma unroll
                for (int j = 0; j < 4; j++) {
                    uint32_t r = (uint32_t)(wn * 64 + j * 16 + (lane & 7) + ((lane & 16) ? 8 : 0));
                    uint32_t off = r * 80u + kb;
                    ldsm_x4(bh + j * 4, aBh + off);
                    ldsm_x4(bl + j * 4, aBl + off);
                }
            }
            // ---- 3-term MMAs ----
#pragma unroll
            for (int i = 0; i < 2; i++) {
#pragma unroll
                for (int j = 0; j < 8; j++) {
                    int bi = (j >> 1) * 4 + (j & 1) * 2;
                    mma16816(d[i][j], ah[i], bh + bi);
                    mma16816(d[i][j], ah[i], bl + bi);
                    mma16816(d[i][j], al[i], bh + bi);
                }
            }
        }
        __syncthreads();
    }

    // ---- epilogue ----
    float* Cbase = (MODE == 0) ? g_node : (MODE == 1) ? g_es : Cout;
#pragma unroll
    for (int i = 0; i < 2; i++) {
        int r0 = blockRow + wm * 32 + i * 16 + (lane >> 2);
        int r1 = r0 + 8;
        bool v0 = r0 < N_NODES, v1 = r1 < N_NODES;
        float s0 = 1.f, s1 = 1.f;
        if (MODE == 1) {
            s0 = v0 ? g_deg[r0] : 0.f;
            s1 = v1 ? g_deg[r1] : 0.f;
        }
        float* c0 = Cbase + (size_t)r0 * D;
        float* c1 = Cbase + (size_t)r1 * D;
#pragma unroll
        for (int j = 0; j < 8; j++) {
            int col = wn * 64 + j * 8 + (lane & 3) * 2;
            float b0 = bias[col], b1 = bias[col + 1];
            if (v0) {
                float2 o = make_float2(d[i][j][0] + s0 * b0, d[i][j][1] + s0 * b1);
                *(float2*)(c0 + col) = o;
            }
            if (v1) {
                float2 o = make_float2(d[i][j][2] + s1 * b0, d[i][j][3] + s1 * b1);
                *(float2*)(c1 + col) = o;
            }
        }
    }
}

// ---------------------------------------------------------------------------
extern "C" void kernel_launch(void* const* d_in, const int* in_sizes, int n_in,
                              void* d_out, int out_size) {
    const float* x  = (const float*)d_in[0];
    const int*   ei = (const int*)d_in[1];
    const float* Wn = (const float*)d_in[2];
    const float* bn = (const float*)d_in[3];
    const float* We = (const float*)d_in[4];
    const float* be = (const float*)d_in[5];
    const float* Wu = (const float*)d_in[6];
    const float* bu = (const float*)d_in[7];
    float* out = (float*)d_out;
    (void)in_sizes; (void)n_in; (void)out_size;

    zero_kernel<<<(N_NODES * D / 4 + 255) / 256, 256>>>();
    prep_weights<<<(3 * D * D + 255) / 256, 256>>>(Wn, We, Wu);

    // 1. node = x @ Wn^T + bn
    mma_gemm<0, 128><<<N_TILES, 256>>>(x, bn, nullptr);

    // 2. nbr_sum / deg scatter (4 edges per warp)
    scatter_kernel<<<(E_EDGES / 4 * 32) / 256, 256>>>(ei);

    // 3. edge_sum = [deg*node | nbr] @ We^T + deg*be
    mma_gemm<1, 256><<<N_TILES, 256>>>(nullptr, be, nullptr);

    // 4. out = gelu([node | nbr | edge_sum]) @ Wu^T + bu
    mma_gemm<2, 384><<<N_TILES, 256>>>(nullptr, bu, out);
}

// round 8
// speedup vs baseline: 2.4581x; 1.0798x over previous
#include <cuda_runtime.h>
#include <cuda_fp16.h>
#include <cstdint>

#define N_NODES 50000
#define D 128
#define E_EDGES 800000
#define M_TILE 128
#define N_TILES ((N_NODES + M_TILE - 1) / M_TILE)   // 391
#define PADK 40                                      // padded row: 40 fp16 = 80B (16B-aligned, conflict-free ldmatrix)

// ---------------- scratch globals (allocation forbidden) -------------------
__device__ __align__(16) float g_node[N_NODES * D];
__device__ __align__(16) float g_nbr [N_NODES * D];
__device__ __align__(16) float g_es  [N_NODES * D];
__device__ __align__(16) float g_deg [N_NODES];
__device__ __align__(16) __half g_Wn_h[D *     D];
__device__ __align__(16) __half g_Wn_l[D *     D];
__device__ __align__(16) __half g_We_h[D * 2 * D];
__device__ __align__(16) __half g_We_l[D * 2 * D];
__device__ __align__(16) __half g_Wu_h[D * 3 * D];
__device__ __align__(16) __half g_Wu_l[D * 3 * D];

// ---------------- helpers ---------------------------------------------------
__device__ __forceinline__ uint32_t smem_u32(const void* p) {
    uint32_t a;
    asm("{ .reg .u64 t; cvta.to.shared.u64 t, %1; cvt.u32.u64 %0, t; }"
        : "=r"(a) : "l"(p));
    return a;
}
__device__ __forceinline__ void sts128(uint32_t addr, uint4 v) {
    asm volatile("st.shared.v4.b32 [%0], {%1, %2, %3, %4};"
                 :: "r"(addr), "r"(v.x), "r"(v.y), "r"(v.z), "r"(v.w) : "memory");
}
__device__ __forceinline__ void ldsm_x4(uint32_t* r, uint32_t addr) {
    asm volatile("ldmatrix.sync.aligned.m8n8.x4.shared.b16 {%0, %1, %2, %3}, [%4];"
                 : "=r"(r[0]), "=r"(r[1]), "=r"(r[2]), "=r"(r[3]) : "r"(addr));
}
__device__ __forceinline__ void mma16816(float* d, const uint32_t* a, const uint32_t* b) {
    asm volatile(
        "mma.sync.aligned.m16n8k16.row.col.f32.f16.f16.f32 "
        "{%0, %1, %2, %3}, {%4, %5, %6, %7}, {%8, %9}, {%0, %1, %2, %3};"
        : "+f"(d[0]), "+f"(d[1]), "+f"(d[2]), "+f"(d[3])
        : "r"(a[0]), "r"(a[1]), "r"(a[2]), "r"(a[3]), "r"(b[0]), "r"(b[1]));
}
__device__ __forceinline__ uint32_t pack_h2(float a, float b) {
    __half2 h = __floats2half2_rn(a, b);
    return *reinterpret_cast<uint32_t*>(&h);
}
__device__ __forceinline__ float gelu_exact(float u) {
    return 0.5f * u * (1.0f + erff(u * 0.70710678118654752f));
}

// ---------------------------------------------------------------------------
__global__ void zero_kernel() {
    int i = blockIdx.x * blockDim.x + threadIdx.x;
    float4 z = make_float4(0.f, 0.f, 0.f, 0.f);
    if (i < N_NODES * D / 4) ((float4*)g_nbr)[i] = z;
    if (i < N_NODES) g_deg[i] = 0.f;
}

// Split weights to fp16 hi/lo (hi = rn(w), lo = rn(w - hi)); layout stays
// [n][K] (K-major = mma ".col" B). B carries ~2^-23 effective precision, so
// the only surviving GEMM error is A's single-fp16 rounding (~2^-12).
__global__ void prep_weights(const float* __restrict__ Wn,
                             const float* __restrict__ We,
                             const float* __restrict__ Wu) {
    int i = blockIdx.x * blockDim.x + threadIdx.x;
    if (i < D * D) {
        float w = Wn[i];
        __half h = __float2half_rn(w);
        g_Wn_h[i] = h; g_Wn_l[i] = __float2half_rn(w - __half2float(h));
    }
    if (i < 2 * D * D) {
        float w = We[i];
        __half h = __float2half_rn(w);
        g_We_h[i] = h; g_We_l[i] = __float2half_rn(w - __half2float(h));
    }
    if (i < 3 * D * D) {
        float w = Wu[i];
        __half h = __float2half_rn(w);
        g_Wu_h[i] = h; g_Wu_l[i] = __float2half_rn(w - __half2float(h));
    }
}

// ---------------------------------------------------------------------------
// Edge scatter: 4 edges per warp (MLP=4 on the row gathers).
__global__ void __launch_bounds__(256) scatter_kernel(const int* __restrict__ ei) {
    int w = (blockIdx.x * blockDim.x + threadIdx.x) >> 5;
    int lane = threadIdx.x & 31;
    int e0 = w * 4;
    if (e0 >= E_EDGES) return;
    int4 s4 = *(const int4*)(ei + e0);
    int4 d4 = *(const int4*)(ei + E_EDGES + e0);
    int src[4] = {s4.x, s4.y, s4.z, s4.w};
    int dst[4] = {d4.x, d4.y, d4.z, d4.w};
    float4 v[4];
#pragma unroll
    for (int i = 0; i < 4; i++)
        v[i] = ((const float4*)(g_node + (size_t)dst[i] * D))[lane];
#pragma unroll
    for (int i = 0; i < 4; i++) {
        float* p = g_nbr + (size_t)src[i] * D + lane * 4;
        asm volatile("red.global.add.v4.f32 [%0], {%1, %2, %3, %4};"
                     :: "l"(p), "f"(v[i].x), "f"(v[i].y), "f"(v[i].z), "f"(v[i].w)
                     : "memory");
    }
    if (lane == 0) {
#pragma unroll
        for (int i = 0; i < 4; i++) atomicAdd(&g_deg[src[i]], 1.0f);
    }
}

// ---------------------------------------------------------------------------
// fp16 HMMA GEMM (A single fp16, B split hi/lo):
//   C[M x 128] = A[M x K] @ W[128][K]^T + bias,  C = A*Bh + A*Bl  (2 MMAs/tile)
// MODE 0: A = x,                        W = Wn, C = g_node, bias = bn
// MODE 1: A = [deg*node | nbr],         W = We, C = g_es,   bias = deg*be
// MODE 2: A = gelu([node | nbr | es]),  W = Wu, C = d_out,  bias = bu
// CTA: 128x128 tile, 256 threads, 8 warps (4x2), warp tile 32x64, BK=32.
template <int MODE, int K>
__global__ void __launch_bounds__(256) mma_gemm(const float* __restrict__ A0,
                                                const float* __restrict__ bias,
                                                float* __restrict__ Cout) {
    __shared__ __align__(16) __half sA [M_TILE * PADK];
    __shared__ __align__(16) __half sBh[D * PADK];
    __shared__ __align__(16) __half sBl[D * PADK];

    const int tid  = threadIdx.x;
    const int lane = tid & 31;
    const int wid  = tid >> 5;
    const int wm   = wid >> 1;          // 0..3  (M)
    const int wn   = wid & 1;           // 0..1  (N)
    const int blockRow = blockIdx.x * M_TILE;

    const uint32_t aA  = smem_u32(sA);
    const uint32_t aBh = smem_u32(sBh), aBl = smem_u32(sBl);

    const __half* WH = (MODE == 0) ? g_Wn_h : (MODE == 1) ? g_We_h : g_Wu_h;
    const __half* WL = (MODE == 0) ? g_Wn_l : (MODE == 1) ? g_We_l : g_Wu_l;

    // ---- per-thread load duty: A row = tid/2, B row n = tid/2, half = tid&1
    const int ldRow = tid >> 1;
    const int half  = tid & 1;
    const int mA    = blockRow + ldRow;
    const bool mvA  = (mA < N_NODES);
    const float degA = (MODE == 1) ? (mvA ? g_deg[mA] : 0.f) : 1.f;

    constexpr int NC = K / 32;

    float d[2][8][4];
#pragma unroll
    for (int i = 0; i < 2; i++)
#pragma unroll
        for (int j = 0; j < 8; j++)
#pragma unroll
            for (int q = 0; q < 4; q++) d[i][j][q] = 0.f;

    float4 aReg[4];
    uint4  bRegH[2], bRegL[2];

    auto loadChunk = [&](int c) {
        // A: 16 fp32 of row mA
        const float* srcp;
        if (MODE == 0) {
            srcp = A0 + (size_t)mA * D + c * 32;
        } else if (MODE == 1) {
            srcp = (c < 4) ? g_node + (size_t)mA * D + c * 32
                           : g_nbr  + (size_t)mA * D + (c - 4) * 32;
        } else {
            int seg = c >> 2;
            const float* b = (seg == 0) ? g_node : (seg == 1) ? g_nbr : g_es;
            srcp = b + (size_t)mA * D + (c & 3) * 32;
        }
        const float4* p4 = (const float4*)(srcp + half * 16);
        if (mvA) {
#pragma unroll
            for (int q = 0; q < 4; q++) aReg[q] = p4[q];
        } else {
            float4 z = make_float4(0.f, 0.f, 0.f, 0.f);
#pragma unroll
            for (int q = 0; q < 4; q++) aReg[q] = z;
        }
        // B: 16 fp16 hi + 16 lo of weight row n = ldRow
        const uint4* ph = (const uint4*)(WH + (size_t)ldRow * K + c * 32 + half * 16);
        const uint4* pl = (const uint4*)(WL + (size_t)ldRow * K + c * 32 + half * 16);
        bRegH[0] = ph[0]; bRegH[1] = ph[1];
        bRegL[0] = pl[0]; bRegL[1] = pl[1];
    };

    auto storeChunk = [&](int c) {
        float scale = 1.f;
        if (MODE == 1) scale = (c < 4) ? degA : 1.f;
        // 16 fp32 -> 16 fp16 (one uint4 per 8 values)
        uint4 H[2];
#pragma unroll
        for (int q = 0; q < 2; q++) {
            float4 fa = aReg[2 * q], fb = aReg[2 * q + 1];
            if (MODE == 1) {
                fa.x *= scale; fa.y *= scale; fa.z *= scale; fa.w *= scale;
                fb.x *= scale; fb.y *= scale; fb.z *= scale; fb.w *= scale;
            }
            if (MODE == 2) {
                fa.x = gelu_exact(fa.x); fa.y = gelu_exact(fa.y);
                fa.z = gelu_exact(fa.z); fa.w = gelu_exact(fa.w);
                fb.x = gelu_exact(fb.x); fb.y = gelu_exact(fb.y);
                fb.z = gelu_exact(fb.z); fb.w = gelu_exact(fb.w);
            }
            H[q].x = pack_h2(fa.x, fa.y);
            H[q].y = pack_h2(fa.z, fa.w);
            H[q].z = pack_h2(fb.x, fb.y);
            H[q].w = pack_h2(fb.z, fb.w);
        }
        uint32_t offA = (uint32_t)ldRow * 80u + half * 32u;
        sts128(aA + offA,      H[0]);
        sts128(aA + offA + 16, H[1]);
        uint32_t offB = (uint32_t)ldRow * 80u + half * 32u;
        sts128(aBh + offB,      bRegH[0]);
        sts128(aBh + offB + 16, bRegH[1]);
        sts128(aBl + offB,      bRegL[0]);
        sts128(aBl + offB + 16, bRegL[1]);
    };

    loadChunk(0);

    for (int c = 0; c < NC; c++) {
        storeChunk(c);
        __syncthreads();
        if (c + 1 < NC) loadChunk(c + 1);   // overlap LDG with MMAs below

#pragma unroll
        for (int ks = 0; ks < 2; ks++) {
            // ---- A fragments, 2 m-tiles ----
            uint32_t ah[2][4];
            {
                uint32_t kb = (uint32_t)(ks * 16 + ((lane >> 4) << 3)) * 2u;
#pragma unroll
                for (int i = 0; i < 2; i++) {
                    uint32_t r = (uint32_t)(wm * 32 + i * 16 + (lane & 15));
                    ldsm_x4(ah[i], aA + r * 80u + kb);
                }
            }
            // ---- B fragments (hi & lo), 8 n-tiles via 4 NON-TRANS x4 loads.
            // Storage is [n][K] (K-contiguous) == mma ".col" layout; each x4
            // covers two adjacent 8-wide n-tiles over k0-15.
            uint32_t bh[16], bl[16];
            {
                uint32_t kb = (uint32_t)(ks * 16 + (lane & 8)) * 2u;
#pragma unroll
                for (int j = 0; j < 4; j++) {
                    uint32_t r = (uint32_t)(wn * 64 + j * 16 + (lane & 7) + ((lane & 16) ? 8 : 0));
                    uint32_t off = r * 80u + kb;
                    ldsm_x4(bh + j * 4, aBh + off);
                    ldsm_x4(bl + j * 4, aBl + off);
                }
            }
            // ---- 2-term MMAs ----
#pragma unroll
            for (int i = 0; i < 2; i++) {
#pragma unroll
                for (int j = 0; j < 8; j++) {
                    int bi = (j >> 1) * 4 + (j & 1) * 2;
                    mma16816(d[i][j], ah[i], bh + bi);
                    mma16816(d[i][j], ah[i], bl + bi);
                }
            }
        }
        __syncthreads();
    }

    // ---- epilogue ----
    float* Cbase = (MODE == 0) ? g_node : (MODE == 1) ? g_es : Cout;
#pragma unroll
    for (int i = 0; i < 2; i++) {
        int r0 = blockRow + wm * 32 + i * 16 + (lane >> 2);
        int r1 = r0 + 8;
        bool v0 = r0 < N_NODES, v1 = r1 < N_NODES;
        float s0 = 1.f, s1 = 1.f;
        if (MODE == 1) {
            s0 = v0 ? g_deg[r0] : 0.f;
            s1 = v1 ? g_deg[r1] : 0.f;
        }
        float* c0 = Cbase + (size_t)r0 * D;
        float* c1 = Cbase + (size_t)r1 * D;
#pragma unroll
        for (int j = 0; j < 8; j++) {
            int col = wn * 64 + j * 8 + (lane & 3) * 2;
            float b0 = bias[col], b1 = bias[col + 1];
            if (v0) {
                float2 o = make_float2(d[i][j][0] + s0 * b0, d[i][j][1] + s0 * b1);
                *(float2*)(c0 + col) = o;
            }
            if (v1) {
                float2 o = make_float2(d[i][j][2] + s1 * b0, d[i][j][3] + s1 * b1);
                *(float2*)(c1 + col) = o;
            }
        }
    }
}

// ---------------------------------------------------------------------------
extern "C" void kernel_launch(void* const* d_in, const int* in_sizes, int n_in,
                              void* d_out, int out_size) {
    const float* x  = (const float*)d_in[0];
    const int*   ei = (const int*)d_in[1];
    const float* Wn = (const float*)d_in[2];
    const float* bn = (const float*)d_in[3];
    const float* We = (const float*)d_in[4];
    const float* be = (const float*)d_in[5];
    const float* Wu = (const float*)d_in[6];
    const float* bu = (const float*)d_in[7];
    float* out = (float*)d_out;
    (void)in_sizes; (void)n_in; (void)out_size;

    zero_kernel<<<(N_NODES * D / 4 + 255) / 256, 256>>>();
    prep_weights<<<(3 * D * D + 255) / 256, 256>>>(Wn, We, Wu);

    // 1. node = x @ Wn^T + bn
    mma_gemm<0, 128><<<N_TILES, 256>>>(x, bn, nullptr);

    // 2. nbr_sum / deg scatter (4 edges per warp)
    scatter_kernel<<<(E_EDGES / 4 * 32) / 256, 256>>>(ei);

    // 3. edge_sum = [deg*node | nbr] @ We^T + deg*be
    mma_gemm<1, 256><<<N_TILES, 256>>>(nullptr, be, nullptr);

    // 4. out = gelu([node | nbr | edge_sum]) @ Wu^T + bu
    mma_gemm<2, 384><<<N_TILES, 256>>>(nullptr, bu, out);
}